// round 6
// baseline (speedup 1.0000x reference)
#include <cuda_runtime.h>
#include <cstdint>

// CFConv: y[idx_i[e]] += x[idx_j[e]] * Wij[e]  (F=64), idx_i sorted.
// E ~ 1.25M, N = 50000.
//
// R5: persistent even partition. 760 blocks (152 SM x 5 CTA) x 8 warps = 6080
// warps, each owns one contiguous ~206-edge span -> zero wave quantization
// (was 3.3 waves, ~17% tail idle). Fewer span-boundary atomics as a bonus.

#define F_DIM 64
#define WPB   8                   // warps per block -> 256 threads
#define THREADS (32 * WPB)
#define NBLOCKS 760               // 152 SMs x 5 CTAs/SM (launch_bounds(256,5))
#define TOTAL_WARPS (NBLOCKS * WPB)

__device__ __forceinline__ void flush_acc(float* __restrict__ y, int cur, int fo,
                                          float2& acc) {
    float* p = y + (long long)cur * F_DIM + fo;
    atomicAdd(p + 0, acc.x);
    atomicAdd(p + 1, acc.y);
    acc.x = 0.f; acc.y = 0.f;
}

__global__ __launch_bounds__(THREADS, 5) void cfconv_kernel(
    const float* __restrict__ x,
    const float* __restrict__ Wij,
    const int* __restrict__ idx_i,
    const int* __restrict__ idx_j,
    float* __restrict__ y,
    long long E, long long span) {
    // Inline idx dtype detection: values < 50000, so int64 (LE) => odd 32-bit
    // words all zero. Broadcast loads, L1/L2-hit, uniform result.
    int all_zero = 1;
    #pragma unroll
    for (int k = 1; k <= 31; k += 2) all_zero &= (__ldg(idx_j + k) == 0);
    const int stride = all_zero ? 2 : 1;

    const int lane = threadIdx.x & 31;
    const long long warp = (long long)blockIdx.x * WPB + (threadIdx.x >> 5);
    long long e0 = warp * span;
    if (e0 >= E) return;
    long long e1 = e0 + span;
    if (e1 > E) e1 = E;

    const int fo = lane * 2;
    const float* __restrict__ wb = Wij + fo;
    const float* __restrict__ xb = x + fo;

    int cur = __ldg(idx_i + e0 * stride);
    float2 acc = make_float2(0.f, 0.f);

    long long base = e0;

    // Prefetch first index batch (coalesced: lane l loads edge base+l).
    int my_i = 0, my_j = 0;
    if (base + 32 <= e1) {
        my_i = __ldg(idx_i + (base + lane) * stride);
        my_j = __ldg(idx_j + (base + lane) * stride);
    }

    for (; base + 32 <= e1; base += 32) {
        int nx_i = 0, nx_j = 0;
        if (base + 64 <= e1) {
            nx_i = __ldg(idx_i + (base + 32 + lane) * stride);
            nx_j = __ldg(idx_j + (base + 32 + lane) * stride);
        }

        #pragma unroll
        for (int k0 = 0; k0 < 32; k0 += 4) {
            int j0 = __shfl_sync(0xFFFFFFFFu, my_j, k0 + 0);
            int j1 = __shfl_sync(0xFFFFFFFFu, my_j, k0 + 1);
            int j2 = __shfl_sync(0xFFFFFFFFu, my_j, k0 + 2);
            int j3 = __shfl_sync(0xFFFFFFFFu, my_j, k0 + 3);

            // Issue all 8 loads before consuming anything (MLP ~ 8).
            float2 w0 = __ldcs((const float2*)(wb + (base + k0 + 0) * F_DIM));
            float2 w1 = __ldcs((const float2*)(wb + (base + k0 + 1) * F_DIM));
            float2 w2 = __ldcs((const float2*)(wb + (base + k0 + 2) * F_DIM));
            float2 w3 = __ldcs((const float2*)(wb + (base + k0 + 3) * F_DIM));
            float2 x0 = __ldg((const float2*)(xb + (long long)j0 * F_DIM));
            float2 x1 = __ldg((const float2*)(xb + (long long)j1 * F_DIM));
            float2 x2 = __ldg((const float2*)(xb + (long long)j2 * F_DIM));
            float2 x3 = __ldg((const float2*)(xb + (long long)j3 * F_DIM));

            int i0 = __shfl_sync(0xFFFFFFFFu, my_i, k0 + 0);
            int i1 = __shfl_sync(0xFFFFFFFFu, my_i, k0 + 1);
            int i2 = __shfl_sync(0xFFFFFFFFu, my_i, k0 + 2);
            int i3 = __shfl_sync(0xFFFFFFFFu, my_i, k0 + 3);

            if (i0 != cur) { flush_acc(y, cur, fo, acc); cur = i0; }
            acc.x += x0.x * w0.x; acc.y += x0.y * w0.y;

            if (i1 != cur) { flush_acc(y, cur, fo, acc); cur = i1; }
            acc.x += x1.x * w1.x; acc.y += x1.y * w1.y;

            if (i2 != cur) { flush_acc(y, cur, fo, acc); cur = i2; }
            acc.x += x2.x * w2.x; acc.y += x2.y * w2.y;

            if (i3 != cur) { flush_acc(y, cur, fo, acc); cur = i3; }
            acc.x += x3.x * w3.x; acc.y += x3.y * w3.y;
        }

        my_i = nx_i;
        my_j = nx_j;
    }

    // Scalar tail (< 32 edges).
    for (; base < e1; ++base) {
        int i = __ldg(idx_i + base * stride);
        int j = __ldg(idx_j + base * stride);
        float2 w  = __ldcs((const float2*)(wb + base * F_DIM));
        float2 xv = __ldg((const float2*)(xb + (long long)j * F_DIM));
        if (i != cur) { flush_acc(y, cur, fo, acc); cur = i; }
        acc.x += xv.x * w.x; acc.y += xv.y * w.y;
    }

    flush_acc(y, cur, fo, acc);
}

extern "C" void kernel_launch(void* const* d_in, const int* in_sizes, int n_in,
                              void* d_out, int out_size) {
    const float* x   = (const float*)d_in[0];
    const float* Wij = (const float*)d_in[1];
    const int*   idx_i = (const int*)d_in[2];
    const int*   idx_j = (const int*)d_in[3];
    float* y = (float*)d_out;

    const long long E = (long long)in_sizes[2];

    cudaMemsetAsync(d_out, 0, (size_t)out_size * sizeof(float));

    const long long span = (E + TOTAL_WARPS - 1) / TOTAL_WARPS;
    cfconv_kernel<<<NBLOCKS, THREADS>>>(x, Wij, idx_i, idx_j, y, E, span);
}